// round 5
// baseline (speedup 1.0000x reference)
#include <cuda_runtime.h>
#include <math.h>

#define NN 100000
#define EE 400000
#define HH 128

// ---- scratch (device globals: allocation-free) ----
__device__ float g_srch[NN * HH];   // src_h  [N,128]
__device__ float g_dsth[NN * HH];   // dst_h  [N,128]
__device__ float g_upd [NN * HH];   // scatter accumulator [N,128]

__device__ __forceinline__ float4 ld4(const float* p) { return *reinterpret_cast<const float4*>(p); }
__device__ __forceinline__ void   st4(float* p, float4 v) { *reinterpret_cast<float4*>(p) = v; }

__device__ __forceinline__ float gelu_exact(float x) {
    return 0.5f * x * (1.0f + erff(x * 0.70710678118654752440f));
}

#define FMA8(ACC, AV, B0, B1)                      \
    ACC[0] = fmaf(AV, B0.x, ACC[0]);               \
    ACC[1] = fmaf(AV, B0.y, ACC[1]);               \
    ACC[2] = fmaf(AV, B0.z, ACC[2]);               \
    ACC[3] = fmaf(AV, B0.w, ACC[3]);               \
    ACC[4] = fmaf(AV, B1.x, ACC[4]);               \
    ACC[5] = fmaf(AV, B1.y, ACC[5]);               \
    ACC[6] = fmaf(AV, B1.z, ACC[6]);               \
    ACC[7] = fmaf(AV, B1.w, ACC[7]);

#define ZERO_ACC(A)                                \
    _Pragma("unroll") for (int _r = 0; _r < 4; _r++) \
    _Pragma("unroll") for (int _j = 0; _j < 8; _j++) A[_r][_j] = 0.0f;

// ---------------------------------------------------------------------------
// 64x128 GEMM tile: C[64,128] = A0[64,128] @ W0[128,128] (+ A1 @ W1 if DUAL)
// A0/A1 in smem (row stride 128). Weights streamed from global in K-chunks of 8.
// Thread map: 256 threads; ty=tid>>4 owns rows ty*4..+3; tx=tid&15 owns cols
// {tx*4..tx*4+3} and {64+tx*4..64+tx*4+3}.
// ---------------------------------------------------------------------------
template <int DUAL>
__device__ __forceinline__ void gemm64(
    const float* __restrict__ A0, const float* __restrict__ A1,
    const float* __restrict__ W0g, const float* __restrict__ W1g,
    float* __restrict__ sW,          // smem, [2][8][128] flat (2048 floats)
    float acc[4][8], int tid)
{
    const int ty = tid >> 4, tx = tid & 15;
    const int wr = tid >> 5;           // weight row 0..7 within chunk
    const int wc = (tid & 31) << 2;    // weight col *4

#pragma unroll 1
    for (int kc = 0; kc < 16; kc++) {
        __syncthreads();
        st4(sW + wr * 128 + wc, ld4(W0g + (kc * 8 + wr) * 128 + wc));
        if (DUAL) st4(sW + 1024 + wr * 128 + wc, ld4(W1g + (kc * 8 + wr) * 128 + wc));
        __syncthreads();
#pragma unroll
        for (int k4 = 0; k4 < 8; k4 += 4) {
            float4 a0[4], a1[4];
#pragma unroll
            for (int r = 0; r < 4; r++) {
                a0[r] = ld4(A0 + (ty * 4 + r) * 128 + kc * 8 + k4);
                if (DUAL) a1[r] = ld4(A1 + (ty * 4 + r) * 128 + kc * 8 + k4);
            }
#pragma unroll
            for (int kk = 0; kk < 4; kk++) {
                const int k = k4 + kk;
                float4 b00 = ld4(sW + k * 128 + tx * 4);
                float4 b01 = ld4(sW + k * 128 + 64 + tx * 4);
#pragma unroll
                for (int r = 0; r < 4; r++) {
                    float av = (&a0[r].x)[kk];
                    FMA8(acc[r], av, b00, b01);
                }
                if (DUAL) {
                    float4 b10 = ld4(sW + 1024 + k * 128 + tx * 4);
                    float4 b11 = ld4(sW + 1024 + k * 128 + 64 + tx * 4);
#pragma unroll
                    for (int r = 0; r < 4; r++) {
                        float av = (&a1[r].x)[kk];
                        FMA8(acc[r], av, b10, b11);
                    }
                }
            }
        }
    }
}

// Dual-OUTPUT variant: accS = A@W0, accD = A@W1 (shares A loads).
__device__ __forceinline__ void gemm64_2w(
    const float* __restrict__ A0,
    const float* __restrict__ W0g, const float* __restrict__ W1g,
    float* __restrict__ sW, float accS[4][8], float accD[4][8], int tid)
{
    const int ty = tid >> 4, tx = tid & 15;
    const int wr = tid >> 5;
    const int wc = (tid & 31) << 2;

#pragma unroll 1
    for (int kc = 0; kc < 16; kc++) {
        __syncthreads();
        st4(sW + wr * 128 + wc, ld4(W0g + (kc * 8 + wr) * 128 + wc));
        st4(sW + 1024 + wr * 128 + wc, ld4(W1g + (kc * 8 + wr) * 128 + wc));
        __syncthreads();
#pragma unroll
        for (int k4 = 0; k4 < 8; k4 += 4) {
            float4 a0[4];
#pragma unroll
            for (int r = 0; r < 4; r++)
                a0[r] = ld4(A0 + (ty * 4 + r) * 128 + kc * 8 + k4);
#pragma unroll
            for (int kk = 0; kk < 4; kk++) {
                const int k = k4 + kk;
                float4 b00 = ld4(sW + k * 128 + tx * 4);
                float4 b01 = ld4(sW + k * 128 + 64 + tx * 4);
                float4 b10 = ld4(sW + 1024 + k * 128 + tx * 4);
                float4 b11 = ld4(sW + 1024 + k * 128 + 64 + tx * 4);
#pragma unroll
                for (int r = 0; r < 4; r++) {
                    float av = (&a0[r].x)[kk];
                    FMA8(accS[r], av, b00, b01);
                    FMA8(accD[r], av, b10, b11);
                }
            }
        }
    }
}

// ---------------------------------------------------------------------------
__global__ void zero_upd_kernel() {
    int i = blockIdx.x * blockDim.x + threadIdx.x;
    if (i < NN * HH / 4) reinterpret_cast<float4*>(g_upd)[i] = make_float4(0.f, 0.f, 0.f, 0.f);
}

// src_h = feat@W_src + b_src ; dst_h = feat@W_dst + b_dst
__global__ __launch_bounds__(256, 2) void node_kernel(
    const float* __restrict__ feat,
    const float* __restrict__ Ws, const float* __restrict__ bs,
    const float* __restrict__ Wd, const float* __restrict__ bd)
{
    __shared__ float sF[64 * 128];
    __shared__ float sW[2 * 1024];
    const int tid = threadIdx.x, warp = tid >> 5, lane = tid & 31;
    const int ty = tid >> 4, tx = tid & 15;
    const size_t row0 = (size_t)blockIdx.x * 64;

#pragma unroll
    for (int i = 0; i < 8; i++) {
        int r = warp + i * 8;
        size_t gr = row0 + r;
        float4 v = make_float4(0.f, 0.f, 0.f, 0.f);
        if (gr < NN) v = ld4(feat + gr * 128 + lane * 4);
        st4(sF + r * 128 + lane * 4, v);
    }
    float accS[4][8], accD[4][8];
    ZERO_ACC(accS); ZERO_ACC(accD);
    gemm64_2w(sF, Ws, Wd, sW, accS, accD, tid);

    float4 bs0 = ld4(bs + tx * 4), bs1 = ld4(bs + 64 + tx * 4);
    float4 bd0 = ld4(bd + tx * 4), bd1 = ld4(bd + 64 + tx * 4);
#pragma unroll
    for (int r = 0; r < 4; r++) {
        size_t gr = row0 + ty * 4 + r;
        if (gr < NN) {
            float4 v;
            v.x = accS[r][0] + bs0.x; v.y = accS[r][1] + bs0.y;
            v.z = accS[r][2] + bs0.z; v.w = accS[r][3] + bs0.w;
            st4(g_srch + gr * 128 + tx * 4, v);
            v.x = accS[r][4] + bs1.x; v.y = accS[r][5] + bs1.y;
            v.z = accS[r][6] + bs1.z; v.w = accS[r][7] + bs1.w;
            st4(g_srch + gr * 128 + 64 + tx * 4, v);
            v.x = accD[r][0] + bd0.x; v.y = accD[r][1] + bd0.y;
            v.z = accD[r][2] + bd0.z; v.w = accD[r][3] + bd0.w;
            st4(g_dsth + gr * 128 + tx * 4, v);
            v.x = accD[r][4] + bd1.x; v.y = accD[r][5] + bd1.y;
            v.z = accD[r][6] + bd1.z; v.w = accD[r][7] + bd1.w;
            st4(g_dsth + gr * 128 + 64 + tx * 4, v);
        }
    }
}

// Fully-fused edge pipeline: 64 edges per CTA (E = 6250 * 64 exactly).
__global__ __launch_bounds__(256, 2) void edge_kernel(
    const int* __restrict__ esrc, const int* __restrict__ edst,
    const float* __restrict__ W1a, const float* __restrict__ W1b, const float* __restrict__ b1,
    const float* __restrict__ W2,  const float* __restrict__ b2,
    const float* __restrict__ W3,  const float* __restrict__ b3,
    const float* __restrict__ lng, const float* __restrict__ lnb,
    const float* __restrict__ Wg1a, const float* __restrict__ Wg1b, const float* __restrict__ bg1,
    const float* __restrict__ Wg2, const float* __restrict__ bg2)
{
    extern __shared__ float dyn[];
    float* sSE = dyn;             // 8192 floats
    float* sDE = dyn + 8192;      // 8192
    float* sH  = dyn + 16384;     // 8192
    float* sW  = dyn + 24576;     // 2048
    int*   sDst = (int*)(dyn + 26624);   // 64

    const int tid = threadIdx.x, warp = tid >> 5, lane = tid & 31;
    const int ty = tid >> 4, tx = tid & 15;
    const int e0 = blockIdx.x * 64;

    if (tid < 64) sDst[tid] = edst[e0 + tid];
#pragma unroll
    for (int i = 0; i < 8; i++) {
        int r = warp + i * 8;
        int sr = esrc[e0 + r];
        int dr = edst[e0 + r];
        st4(sSE + r * 128 + lane * 4, ld4(g_srch + (size_t)sr * 128 + lane * 4));
        st4(sDE + r * 128 + lane * 4, ld4(g_dsth + (size_t)dr * 128 + lane * 4));
    }
    // (gemm64's leading __syncthreads orders gather writes before reads)

    float acc[4][8];

    // ---- h1 = gelu(se@W1a + de@W1b + b1) -> sH ----
    ZERO_ACC(acc);
    gemm64<1>(sSE, sDE, W1a, W1b, sW, acc, tid);
    {
        float4 bb0 = ld4(b1 + tx * 4), bb1 = ld4(b1 + 64 + tx * 4);
#pragma unroll
        for (int r = 0; r < 4; r++) {
            int row = ty * 4 + r;
            float4 h;
            h.x = gelu_exact(acc[r][0] + bb0.x); h.y = gelu_exact(acc[r][1] + bb0.y);
            h.z = gelu_exact(acc[r][2] + bb0.z); h.w = gelu_exact(acc[r][3] + bb0.w);
            st4(sH + row * 128 + tx * 4, h);
            h.x = gelu_exact(acc[r][4] + bb1.x); h.y = gelu_exact(acc[r][5] + bb1.y);
            h.z = gelu_exact(acc[r][6] + bb1.z); h.w = gelu_exact(acc[r][7] + bb1.w);
            st4(sH + row * 128 + 64 + tx * 4, h);
        }
    }

    // ---- gate = sigmoid(gelu(se@Wg1a + de@Wg1b + bg1) @ Wg2 + bg2) ----
    ZERO_ACC(acc);
    gemm64<1>(sSE, sDE, Wg1a, Wg1b, sW, acc, tid);
    float gate[4];
    {
        float4 bb0 = ld4(bg1 + tx * 4), bb1 = ld4(bg1 + 64 + tx * 4);
        float4 w0  = ld4(Wg2 + tx * 4), w1  = ld4(Wg2 + 64 + tx * 4);
        float bg2v = bg2[0];
#pragma unroll
        for (int r = 0; r < 4; r++) {
            float s = gelu_exact(acc[r][0] + bb0.x) * w0.x
                    + gelu_exact(acc[r][1] + bb0.y) * w0.y
                    + gelu_exact(acc[r][2] + bb0.z) * w0.z
                    + gelu_exact(acc[r][3] + bb0.w) * w0.w
                    + gelu_exact(acc[r][4] + bb1.x) * w1.x
                    + gelu_exact(acc[r][5] + bb1.y) * w1.y
                    + gelu_exact(acc[r][6] + bb1.z) * w1.z
                    + gelu_exact(acc[r][7] + bb1.w) * w1.w;
#pragma unroll
            for (int off = 1; off < 16; off <<= 1)
                s += __shfl_xor_sync(0xffffffffu, s, off);
            gate[r] = 1.0f / (1.0f + expf(-(s + bg2v)));
        }
    }

    // ---- h2 = gelu(h1@W2 + b2) -> sH (overwrite after barrier) ----
    ZERO_ACC(acc);
    gemm64<0>(sH, sH, W2, W2, sW, acc, tid);
    __syncthreads();   // all reads of h1 done before overwrite
    {
        float4 bb0 = ld4(b2 + tx * 4), bb1 = ld4(b2 + 64 + tx * 4);
#pragma unroll
        for (int r = 0; r < 4; r++) {
            int row = ty * 4 + r;
            float4 h;
            h.x = gelu_exact(acc[r][0] + bb0.x); h.y = gelu_exact(acc[r][1] + bb0.y);
            h.z = gelu_exact(acc[r][2] + bb0.z); h.w = gelu_exact(acc[r][3] + bb0.w);
            st4(sH + row * 128 + tx * 4, h);
            h.x = gelu_exact(acc[r][4] + bb1.x); h.y = gelu_exact(acc[r][5] + bb1.y);
            h.z = gelu_exact(acc[r][6] + bb1.z); h.w = gelu_exact(acc[r][7] + bb1.w);
            st4(sH + row * 128 + 64 + tx * 4, h);
        }
    }

    // ---- m = layernorm(h2@W3 + b3); msg = gate*m; scatter-add ----
    ZERO_ACC(acc);
    gemm64<0>(sH, sH, W3, W3, sW, acc, tid);
    {
        float4 b30 = ld4(b3 + tx * 4),  b31 = ld4(b3 + 64 + tx * 4);
        float4 g0  = ld4(lng + tx * 4), g1  = ld4(lng + 64 + tx * 4);
        float4 e0v = ld4(lnb + tx * 4), e1v = ld4(lnb + 64 + tx * 4);
#pragma unroll
        for (int r = 0; r < 4; r++) {
            float x[8];
            x[0] = acc[r][0] + b30.x; x[1] = acc[r][1] + b30.y;
            x[2] = acc[r][2] + b30.z; x[3] = acc[r][3] + b30.w;
            x[4] = acc[r][4] + b31.x; x[5] = acc[r][5] + b31.y;
            x[6] = acc[r][6] + b31.z; x[7] = acc[r][7] + b31.w;
            float s = 0.f, ss = 0.f;
#pragma unroll
            for (int j = 0; j < 8; j++) { s += x[j]; ss += x[j] * x[j]; }
#pragma unroll
            for (int off = 1; off < 16; off <<= 1) {
                s  += __shfl_xor_sync(0xffffffffu, s, off);
                ss += __shfl_xor_sync(0xffffffffu, ss, off);
            }
            float m = s * 0.0078125f;
            float var = ss * 0.0078125f - m * m;
            float rstd = rsqrtf(var + 1e-5f);
            float gv = gate[r];
            float* up = g_upd + (size_t)sDst[ty * 4 + r] * 128;
            atomicAdd(up + tx * 4 + 0,      ((x[0] - m) * rstd * g0.x + e0v.x) * gv);
            atomicAdd(up + tx * 4 + 1,      ((x[1] - m) * rstd * g0.y + e0v.y) * gv);
            atomicAdd(up + tx * 4 + 2,      ((x[2] - m) * rstd * g0.z + e0v.z) * gv);
            atomicAdd(up + tx * 4 + 3,      ((x[3] - m) * rstd * g0.w + e0v.w) * gv);
            atomicAdd(up + 64 + tx * 4 + 0, ((x[4] - m) * rstd * g1.x + e1v.x) * gv);
            atomicAdd(up + 64 + tx * 4 + 1, ((x[5] - m) * rstd * g1.y + e1v.y) * gv);
            atomicAdd(up + 64 + tx * 4 + 2, ((x[6] - m) * rstd * g1.z + e1v.z) * gv);
            atomicAdd(up + 64 + tx * 4 + 3, ((x[7] - m) * rstd * g1.w + e1v.w) * gv);
        }
    }
}

// out = upd@W_out + b_out
__global__ __launch_bounds__(256, 2) void out_kernel(
    const float* __restrict__ Wout, const float* __restrict__ bout,
    float* __restrict__ out)
{
    __shared__ float sU[64 * 128];
    __shared__ float sW[1024];
    const int tid = threadIdx.x, warp = tid >> 5, lane = tid & 31;
    const int ty = tid >> 4, tx = tid & 15;
    const size_t row0 = (size_t)blockIdx.x * 64;

#pragma unroll
    for (int i = 0; i < 8; i++) {
        int r = warp + i * 8;
        size_t gr = row0 + r;
        float4 v = make_float4(0.f, 0.f, 0.f, 0.f);
        if (gr < NN) v = ld4(g_upd + gr * 128 + lane * 4);
        st4(sU + r * 128 + lane * 4, v);
    }
    float acc[4][8];
    ZERO_ACC(acc);
    gemm64<0>(sU, sU, Wout, Wout, sW, acc, tid);

    float4 b0 = ld4(bout + tx * 4), b1v = ld4(bout + 64 + tx * 4);
#pragma unroll
    for (int r = 0; r < 4; r++) {
        size_t gr = row0 + ty * 4 + r;
        if (gr < NN) {
            float4 v;
            v.x = acc[r][0] + b0.x; v.y = acc[r][1] + b0.y;
            v.z = acc[r][2] + b0.z; v.w = acc[r][3] + b0.w;
            st4(out + gr * 128 + tx * 4, v);
            v.x = acc[r][4] + b1v.x; v.y = acc[r][5] + b1v.y;
            v.z = acc[r][6] + b1v.z; v.w = acc[r][7] + b1v.w;
            st4(out + gr * 128 + 64 + tx * 4, v);
        }
    }
}

static const int EDGE_SMEM = (8192 * 3 + 2048) * 4 + 64 * 4;  // 106,752 B

extern "C" void kernel_launch(void* const* d_in, const int* in_sizes, int n_in,
                              void* d_out, int out_size)
{
    const float* feat  = (const float*)d_in[0];
    const int*   esrc  = (const int*)d_in[1];
    const int*   edst  = (const int*)d_in[2];
    const float* W_src = (const float*)d_in[3];
    const float* b_src = (const float*)d_in[4];
    const float* W_dst = (const float*)d_in[5];
    const float* b_dst = (const float*)d_in[6];
    const float* W1a   = (const float*)d_in[7];
    const float* W1b   = (const float*)d_in[8];
    const float* b1    = (const float*)d_in[9];
    const float* W2    = (const float*)d_in[10];
    const float* b2    = (const float*)d_in[11];
    const float* W3    = (const float*)d_in[12];
    const float* b3    = (const float*)d_in[13];
    const float* ln_g  = (const float*)d_in[14];
    const float* ln_b  = (const float*)d_in[15];
    const float* Wg1a  = (const float*)d_in[16];
    const float* Wg1b  = (const float*)d_in[17];
    const float* bg1   = (const float*)d_in[18];
    const float* Wg2   = (const float*)d_in[19];
    const float* bg2   = (const float*)d_in[20];
    const float* W_out = (const float*)d_in[21];
    const float* b_out = (const float*)d_in[22];
    float* out = (float*)d_out;

    cudaFuncSetAttribute(edge_kernel, cudaFuncAttributeMaxDynamicSharedMemorySize, EDGE_SMEM);

    zero_upd_kernel<<<(NN * HH / 4 + 255) / 256, 256>>>();
    node_kernel<<<(NN + 63) / 64, 256>>>(feat, W_src, b_src, W_dst, b_dst);
    edge_kernel<<<EE / 64, 256, EDGE_SMEM>>>(esrc, edst, W1a, W1b, b1, W2, b2, W3, b3,
                                             ln_g, ln_b, Wg1a, Wg1b, bg1, Wg2, bg2);
    out_kernel<<<(NN + 63) / 64, 256>>>(W_out, b_out, out);
}

// round 7
// speedup vs baseline: 1.0622x; 1.0622x over previous
#include <cuda_runtime.h>
#include <math.h>

#define NN 100000
#define EE 400000
#define HH 128

typedef unsigned long long u64;

// ---- scratch (device globals: allocation-free) ----
__device__ float g_srch[NN * HH];   // src_h  [N,128]
__device__ float g_dsth[NN * HH];   // dst_h  [N,128]
__device__ float g_upd [NN * HH];   // scatter accumulator [N,128]

__device__ __forceinline__ float4 ld4(const float* p) { return *reinterpret_cast<const float4*>(p); }
__device__ __forceinline__ void   st4(float* p, float4 v) { *reinterpret_cast<float4*>(p) = v; }

// 16B smem load viewed as two packed f32x2 operands (register pairs, no movs)
__device__ __forceinline__ ulonglong2 ld2u64(const float* p) {
    return *reinterpret_cast<const ulonglong2*>(p);
}

// packed-fp32 helpers (sm_100+ f32x2 ops, PTX-only)
__device__ __forceinline__ u64 bcast2(float a) {
    u64 r; asm("mov.b64 %0, {%1, %1};" : "=l"(r) : "f"(a)); return r;
}
__device__ __forceinline__ void ffma2(u64& d, u64 a, u64 b) {
    asm("fma.rn.f32x2 %0, %1, %2, %0;" : "+l"(d) : "l"(a), "l"(b));
}
__device__ __forceinline__ float2 unpk(u64 v) {
    float2 f; asm("mov.b64 {%0, %1}, %2;" : "=f"(f.x), "=f"(f.y) : "l"(v)); return f;
}

__device__ __forceinline__ float gelu_exact(float x) {
    return 0.5f * x * (1.0f + erff(x * 0.70710678118654752440f));
}

// acc[r][0..3] = packed col-pairs {(c0,c1),(c2,c3),(c4,c5),(c6,c7)}
#define PFMA8(ACC, AP, BA, BB)       \
    ffma2(ACC[0], AP, BA.x);         \
    ffma2(ACC[1], AP, BA.y);         \
    ffma2(ACC[2], AP, BB.x);         \
    ffma2(ACC[3], AP, BB.y);

#define ZERO_ACC2(A)                                  \
    _Pragma("unroll") for (int _r = 0; _r < 4; _r++)  \
    _Pragma("unroll") for (int _j = 0; _j < 4; _j++) A[_r][_j] = 0ULL;

// unpack one row of packed accumulators into 8 scalars
#define UNPACK8(X, ACCR)                       \
    { float2 _p;                               \
      _p = unpk(ACCR[0]); X[0] = _p.x; X[1] = _p.y; \
      _p = unpk(ACCR[1]); X[2] = _p.x; X[3] = _p.y; \
      _p = unpk(ACCR[2]); X[4] = _p.x; X[5] = _p.y; \
      _p = unpk(ACCR[3]); X[6] = _p.x; X[7] = _p.y; }

// ---------------------------------------------------------------------------
// 64x128 GEMM tile (packed f32x2): C[64,128] = A0@W0 (+ A1@W1 if DUAL)
// ---------------------------------------------------------------------------
template <int DUAL>
__device__ __forceinline__ void gemm64p(
    const float* __restrict__ A0, const float* __restrict__ A1,
    const float* __restrict__ W0g, const float* __restrict__ W1g,
    float* __restrict__ sW,          // smem, 2048 floats
    u64 acc[4][4], int tid)
{
    const int ty = tid >> 4, tx = tid & 15;
    const int wr = tid >> 5;           // weight row 0..7 within chunk
    const int wc = (tid & 31) << 2;    // weight col *4

#pragma unroll 1
    for (int kc = 0; kc < 16; kc++) {
        __syncthreads();
        st4(sW + wr * 128 + wc, ld4(W0g + (kc * 8 + wr) * 128 + wc));
        if (DUAL) st4(sW + 1024 + wr * 128 + wc, ld4(W1g + (kc * 8 + wr) * 128 + wc));
        __syncthreads();
#pragma unroll
        for (int k4 = 0; k4 < 8; k4 += 4) {
            float4 a0[4], a1[4];
#pragma unroll
            for (int r = 0; r < 4; r++) {
                a0[r] = ld4(A0 + (ty * 4 + r) * 128 + kc * 8 + k4);
                if (DUAL) a1[r] = ld4(A1 + (ty * 4 + r) * 128 + kc * 8 + k4);
            }
#pragma unroll
            for (int kk = 0; kk < 4; kk++) {
                const int k = k4 + kk;
                ulonglong2 b0a = ld2u64(sW + k * 128 + tx * 4);
                ulonglong2 b0b = ld2u64(sW + k * 128 + 64 + tx * 4);
#pragma unroll
                for (int r = 0; r < 4; r++) {
                    u64 ap = bcast2((&a0[r].x)[kk]);
                    PFMA8(acc[r], ap, b0a, b0b);
                }
                if (DUAL) {
                    ulonglong2 b1a = ld2u64(sW + 1024 + k * 128 + tx * 4);
                    ulonglong2 b1b = ld2u64(sW + 1024 + k * 128 + 64 + tx * 4);
#pragma unroll
                    for (int r = 0; r < 4; r++) {
                        u64 ap = bcast2((&a1[r].x)[kk]);
                        PFMA8(acc[r], ap, b1a, b1b);
                    }
                }
            }
        }
    }
}

// Dual-OUTPUT variant: accS = A@W0, accD = A@W1 (shares A loads).
__device__ __forceinline__ void gemm64p_2w(
    const float* __restrict__ A0,
    const float* __restrict__ W0g, const float* __restrict__ W1g,
    float* __restrict__ sW, u64 accS[4][4], u64 accD[4][4], int tid)
{
    const int ty = tid >> 4, tx = tid & 15;
    const int wr = tid >> 5;
    const int wc = (tid & 31) << 2;

#pragma unroll 1
    for (int kc = 0; kc < 16; kc++) {
        __syncthreads();
        st4(sW + wr * 128 + wc, ld4(W0g + (kc * 8 + wr) * 128 + wc));
        st4(sW + 1024 + wr * 128 + wc, ld4(W1g + (kc * 8 + wr) * 128 + wc));
        __syncthreads();
#pragma unroll
        for (int k4 = 0; k4 < 8; k4 += 4) {
            float4 a0[4];
#pragma unroll
            for (int r = 0; r < 4; r++)
                a0[r] = ld4(A0 + (ty * 4 + r) * 128 + kc * 8 + k4);
#pragma unroll
            for (int kk = 0; kk < 4; kk++) {
                const int k = k4 + kk;
                ulonglong2 b0a = ld2u64(sW + k * 128 + tx * 4);
                ulonglong2 b0b = ld2u64(sW + k * 128 + 64 + tx * 4);
                ulonglong2 b1a = ld2u64(sW + 1024 + k * 128 + tx * 4);
                ulonglong2 b1b = ld2u64(sW + 1024 + k * 128 + 64 + tx * 4);
#pragma unroll
                for (int r = 0; r < 4; r++) {
                    u64 ap = bcast2((&a0[r].x)[kk]);
                    PFMA8(accS[r], ap, b0a, b0b);
                    PFMA8(accD[r], ap, b1a, b1b);
                }
            }
        }
    }
}

// ---------------------------------------------------------------------------
__global__ void zero_upd_kernel() {
    int i = blockIdx.x * blockDim.x + threadIdx.x;
    if (i < NN * HH / 4) reinterpret_cast<float4*>(g_upd)[i] = make_float4(0.f, 0.f, 0.f, 0.f);
}

// src_h = feat@W_src + b_src ; dst_h = feat@W_dst + b_dst
__global__ __launch_bounds__(256, 2) void node_kernel(
    const float* __restrict__ feat,
    const float* __restrict__ Ws, const float* __restrict__ bs,
    const float* __restrict__ Wd, const float* __restrict__ bd)
{
    __shared__ float sF[64 * 128];
    __shared__ float sW[2 * 1024];
    const int tid = threadIdx.x, warp = tid >> 5, lane = tid & 31;
    const int ty = tid >> 4, tx = tid & 15;
    const size_t row0 = (size_t)blockIdx.x * 64;

#pragma unroll
    for (int i = 0; i < 8; i++) {
        int r = warp + i * 8;
        size_t gr = row0 + r;
        float4 v = make_float4(0.f, 0.f, 0.f, 0.f);
        if (gr < NN) v = ld4(feat + gr * 128 + lane * 4);
        st4(sF + r * 128 + lane * 4, v);
    }
    u64 accS[4][4], accD[4][4];
    ZERO_ACC2(accS); ZERO_ACC2(accD);
    gemm64p_2w(sF, Ws, Wd, sW, accS, accD, tid);

    float4 bs0 = ld4(bs + tx * 4), bs1 = ld4(bs + 64 + tx * 4);
    float4 bd0 = ld4(bd + tx * 4), bd1 = ld4(bd + 64 + tx * 4);
#pragma unroll
    for (int r = 0; r < 4; r++) {
        size_t gr = row0 + ty * 4 + r;
        if (gr < NN) {
            float xs[8], xd[8];
            UNPACK8(xs, accS[r]); UNPACK8(xd, accD[r]);
            float4 v;
            v.x = xs[0] + bs0.x; v.y = xs[1] + bs0.y;
            v.z = xs[2] + bs0.z; v.w = xs[3] + bs0.w;
            st4(g_srch + gr * 128 + tx * 4, v);
            v.x = xs[4] + bs1.x; v.y = xs[5] + bs1.y;
            v.z = xs[6] + bs1.z; v.w = xs[7] + bs1.w;
            st4(g_srch + gr * 128 + 64 + tx * 4, v);
            v.x = xd[0] + bd0.x; v.y = xd[1] + bd0.y;
            v.z = xd[2] + bd0.z; v.w = xd[3] + bd0.w;
            st4(g_dsth + gr * 128 + tx * 4, v);
            v.x = xd[4] + bd1.x; v.y = xd[5] + bd1.y;
            v.z = xd[6] + bd1.z; v.w = xd[7] + bd1.w;
            st4(g_dsth + gr * 128 + 64 + tx * 4, v);
        }
    }
}

// Fully-fused edge pipeline: 64 edges per CTA (E = 6250 * 64 exactly).
__global__ __launch_bounds__(256, 2) void edge_kernel(
    const int* __restrict__ esrc, const int* __restrict__ edst,
    const float* __restrict__ W1a, const float* __restrict__ W1b, const float* __restrict__ b1,
    const float* __restrict__ W2,  const float* __restrict__ b2,
    const float* __restrict__ W3,  const float* __restrict__ b3,
    const float* __restrict__ lng, const float* __restrict__ lnb,
    const float* __restrict__ Wg1a, const float* __restrict__ Wg1b, const float* __restrict__ bg1,
    const float* __restrict__ Wg2, const float* __restrict__ bg2)
{
    extern __shared__ float dyn[];
    float* sSE = dyn;             // 8192 floats
    float* sDE = dyn + 8192;      // 8192
    float* sH  = dyn + 16384;     // 8192
    float* sW  = dyn + 24576;     // 2048
    int*   sDst = (int*)(dyn + 26624);   // 64

    const int tid = threadIdx.x, warp = tid >> 5, lane = tid & 31;
    const int ty = tid >> 4, tx = tid & 15;
    const int e0 = blockIdx.x * 64;

    if (tid < 64) sDst[tid] = edst[e0 + tid];
#pragma unroll
    for (int i = 0; i < 8; i++) {
        int r = warp + i * 8;
        int sr = esrc[e0 + r];
        int dr = edst[e0 + r];
        st4(sSE + r * 128 + lane * 4, ld4(g_srch + (size_t)sr * 128 + lane * 4));
        st4(sDE + r * 128 + lane * 4, ld4(g_dsth + (size_t)dr * 128 + lane * 4));
    }
    // (gemm64p's leading __syncthreads orders gather writes before reads)

    u64 acc[4][4];

    // ---- h1 = gelu(se@W1a + de@W1b + b1) -> sH ----
    ZERO_ACC2(acc);
    gemm64p<1>(sSE, sDE, W1a, W1b, sW, acc, tid);
    {
        float4 bb0 = ld4(b1 + tx * 4), bb1 = ld4(b1 + 64 + tx * 4);
#pragma unroll
        for (int r = 0; r < 4; r++) {
            int row = ty * 4 + r;
            float x[8]; UNPACK8(x, acc[r]);
            float4 h;
            h.x = gelu_exact(x[0] + bb0.x); h.y = gelu_exact(x[1] + bb0.y);
            h.z = gelu_exact(x[2] + bb0.z); h.w = gelu_exact(x[3] + bb0.w);
            st4(sH + row * 128 + tx * 4, h);
            h.x = gelu_exact(x[4] + bb1.x); h.y = gelu_exact(x[5] + bb1.y);
            h.z = gelu_exact(x[6] + bb1.z); h.w = gelu_exact(x[7] + bb1.w);
            st4(sH + row * 128 + 64 + tx * 4, h);
        }
    }

    // ---- gate = sigmoid(gelu(se@Wg1a + de@Wg1b + bg1) @ Wg2 + bg2) ----
    ZERO_ACC2(acc);
    gemm64p<1>(sSE, sDE, Wg1a, Wg1b, sW, acc, tid);
    float gate[4];
    {
        float4 bb0 = ld4(bg1 + tx * 4), bb1 = ld4(bg1 + 64 + tx * 4);
        float4 w0  = ld4(Wg2 + tx * 4), w1  = ld4(Wg2 + 64 + tx * 4);
        float bg2v = bg2[0];
#pragma unroll
        for (int r = 0; r < 4; r++) {
            float x[8]; UNPACK8(x, acc[r]);
            float s = gelu_exact(x[0] + bb0.x) * w0.x
                    + gelu_exact(x[1] + bb0.y) * w0.y
                    + gelu_exact(x[2] + bb0.z) * w0.z
                    + gelu_exact(x[3] + bb0.w) * w0.w
                    + gelu_exact(x[4] + bb1.x) * w1.x
                    + gelu_exact(x[5] + bb1.y) * w1.y
                    + gelu_exact(x[6] + bb1.z) * w1.z
                    + gelu_exact(x[7] + bb1.w) * w1.w;
#pragma unroll
            for (int off = 1; off < 16; off <<= 1)
                s += __shfl_xor_sync(0xffffffffu, s, off);
            gate[r] = 1.0f / (1.0f + expf(-(s + bg2v)));
        }
    }

    // ---- h2 = gelu(h1@W2 + b2) -> sH (overwrite after barrier) ----
    ZERO_ACC2(acc);
    gemm64p<0>(sH, sH, W2, W2, sW, acc, tid);
    __syncthreads();   // all reads of h1 done before overwrite
    {
        float4 bb0 = ld4(b2 + tx * 4), bb1 = ld4(b2 + 64 + tx * 4);
#pragma unroll
        for (int r = 0; r < 4; r++) {
            int row = ty * 4 + r;
            float x[8]; UNPACK8(x, acc[r]);
            float4 h;
            h.x = gelu_exact(x[0] + bb0.x); h.y = gelu_exact(x[1] + bb0.y);
            h.z = gelu_exact(x[2] + bb0.z); h.w = gelu_exact(x[3] + bb0.w);
            st4(sH + row * 128 + tx * 4, h);
            h.x = gelu_exact(x[4] + bb1.x); h.y = gelu_exact(x[5] + bb1.y);
            h.z = gelu_exact(x[6] + bb1.z); h.w = gelu_exact(x[7] + bb1.w);
            st4(sH + row * 128 + 64 + tx * 4, h);
        }
    }

    // ---- m = layernorm(h2@W3 + b3); msg = gate*m; scatter-add ----
    ZERO_ACC2(acc);
    gemm64p<0>(sH, sH, W3, W3, sW, acc, tid);
    {
        float4 b30 = ld4(b3 + tx * 4),  b31 = ld4(b3 + 64 + tx * 4);
        float4 g0  = ld4(lng + tx * 4), g1  = ld4(lng + 64 + tx * 4);
        float4 e0v = ld4(lnb + tx * 4), e1v = ld4(lnb + 64 + tx * 4);
#pragma unroll
        for (int r = 0; r < 4; r++) {
            float x[8]; UNPACK8(x, acc[r]);
            x[0] += b30.x; x[1] += b30.y; x[2] += b30.z; x[3] += b30.w;
            x[4] += b31.x; x[5] += b31.y; x[6] += b31.z; x[7] += b31.w;
            float s = 0.f, ss = 0.f;
#pragma unroll
            for (int j = 0; j < 8; j++) { s += x[j]; ss += x[j] * x[j]; }
#pragma unroll
            for (int off = 1; off < 16; off <<= 1) {
                s  += __shfl_xor_sync(0xffffffffu, s, off);
                ss += __shfl_xor_sync(0xffffffffu, ss, off);
            }
            float m = s * 0.0078125f;
            float var = ss * 0.0078125f - m * m;
            float rstd = rsqrtf(var + 1e-5f);
            float gv = gate[r];
            float* up = g_upd + (size_t)sDst[ty * 4 + r] * 128;
            atomicAdd(up + tx * 4 + 0,      ((x[0] - m) * rstd * g0.x + e0v.x) * gv);
            atomicAdd(up + tx * 4 + 1,      ((x[1] - m) * rstd * g0.y + e0v.y) * gv);
            atomicAdd(up + tx * 4 + 2,      ((x[2] - m) * rstd * g0.z + e0v.z) * gv);
            atomicAdd(up + tx * 4 + 3,      ((x[3] - m) * rstd * g0.w + e0v.w) * gv);
            atomicAdd(up + 64 + tx * 4 + 0, ((x[4] - m) * rstd * g1.x + e1v.x) * gv);
            atomicAdd(up + 64 + tx * 4 + 1, ((x[5] - m) * rstd * g1.y + e1v.y) * gv);
            atomicAdd(up + 64 + tx * 4 + 2, ((x[6] - m) * rstd * g1.z + e1v.z) * gv);
            atomicAdd(up + 64 + tx * 4 + 3, ((x[7] - m) * rstd * g1.w + e1v.w) * gv);
        }
    }
}

// out = upd@W_out + b_out
__global__ __launch_bounds__(256, 2) void out_kernel(
    const float* __restrict__ Wout, const float* __restrict__ bout,
    float* __restrict__ out)
{
    __shared__ float sU[64 * 128];
    __shared__ float sW[1024];
    const int tid = threadIdx.x, warp = tid >> 5, lane = tid & 31;
    const int ty = tid >> 4, tx = tid & 15;
    const size_t row0 = (size_t)blockIdx.x * 64;

#pragma unroll
    for (int i = 0; i < 8; i++) {
        int r = warp + i * 8;
        size_t gr = row0 + r;
        float4 v = make_float4(0.f, 0.f, 0.f, 0.f);
        if (gr < NN) v = ld4(g_upd + gr * 128 + lane * 4);
        st4(sU + r * 128 + lane * 4, v);
    }
    u64 acc[4][4];
    ZERO_ACC2(acc);
    gemm64p<0>(sU, sU, Wout, Wout, sW, acc, tid);

    float4 b0 = ld4(bout + tx * 4), b1v = ld4(bout + 64 + tx * 4);
#pragma unroll
    for (int r = 0; r < 4; r++) {
        size_t gr = row0 + ty * 4 + r;
        if (gr < NN) {
            float x[8]; UNPACK8(x, acc[r]);
            float4 v;
            v.x = x[0] + b0.x; v.y = x[1] + b0.y;
            v.z = x[2] + b0.z; v.w = x[3] + b0.w;
            st4(out + gr * 128 + tx * 4, v);
            v.x = x[4] + b1v.x; v.y = x[5] + b1v.y;
            v.z = x[6] + b1v.z; v.w = x[7] + b1v.w;
            st4(out + gr * 128 + 64 + tx * 4, v);
        }
    }
}

static const int EDGE_SMEM = (8192 * 3 + 2048) * 4 + 64 * 4;  // 106,752 B

extern "C" void kernel_launch(void* const* d_in, const int* in_sizes, int n_in,
                              void* d_out, int out_size)
{
    const float* feat  = (const float*)d_in[0];
    const int*   esrc  = (const int*)d_in[1];
    const int*   edst  = (const int*)d_in[2];
    const float* W_src = (const float*)d_in[3];
    const float* b_src = (const float*)d_in[4];
    const float* W_dst = (const float*)d_in[5];
    const float* b_dst = (const float*)d_in[6];
    const float* W1a   = (const float*)d_in[7];
    const float* W1b   = (const float*)d_in[8];
    const float* b1    = (const float*)d_in[9];
    const float* W2    = (const float*)d_in[10];
    const float* b2    = (const float*)d_in[11];
    const float* W3    = (const float*)d_in[12];
    const float* b3    = (const float*)d_in[13];
    const float* ln_g  = (const float*)d_in[14];
    const float* ln_b  = (const float*)d_in[15];
    const float* Wg1a  = (const float*)d_in[16];
    const float* Wg1b  = (const float*)d_in[17];
    const float* bg1   = (const float*)d_in[18];
    const float* Wg2   = (const float*)d_in[19];
    const float* bg2   = (const float*)d_in[20];
    const float* W_out = (const float*)d_in[21];
    const float* b_out = (const float*)d_in[22];
    float* out = (float*)d_out;

    cudaFuncSetAttribute(edge_kernel, cudaFuncAttributeMaxDynamicSharedMemorySize, EDGE_SMEM);

    zero_upd_kernel<<<(NN * HH / 4 + 255) / 256, 256>>>();
    node_kernel<<<(NN + 63) / 64, 256>>>(feat, W_src, b_src, W_dst, b_dst);
    edge_kernel<<<EE / 64, 256, EDGE_SMEM>>>(esrc, edst, W1a, W1b, b1, W2, b2, W3, b3,
                                             ln_g, ln_b, Wg1a, Wg1b, bg1, Wg2, bg2);
    out_kernel<<<(NN + 63) / 64, 256>>>(W_out, b_out, out);
}

// round 9
// speedup vs baseline: 2.0145x; 1.8966x over previous
#include <cuda_runtime.h>
#include <math.h>

#define NN 100000
#define EE 400000
#define HH 128

typedef unsigned long long u64;

// ---- scratch (device globals: allocation-free) ----
__device__ float g_upd[NN * HH];        // scatter accumulator [N,128]
__device__ float g_Us[NN * 256];        // per-node src tables: [U1s | Ugs]
__device__ float g_Ud[NN * 256];        // per-node dst tables: [U1d | Ugd]
__device__ float g_As[128 * 128];       // W_src@W1a
__device__ float g_Gs[128 * 128];       // W_src@Wg1a
__device__ float g_Ad[128 * 128];       // W_dst@W1b
__device__ float g_Gd[128 * 128];       // W_dst@Wg1b
__device__ float g_fb[4][128];          // folded biases: b_src@W1a, b_src@Wg1a, b_dst@W1b, b_dst@Wg1b

__device__ __forceinline__ float4 ld4(const float* p) { return *reinterpret_cast<const float4*>(p); }
__device__ __forceinline__ void   st4(float* p, float4 v) { *reinterpret_cast<float4*>(p) = v; }
__device__ __forceinline__ ulonglong2 ld2u64(const float* p) {
    return *reinterpret_cast<const ulonglong2*>(p);
}

__device__ __forceinline__ u64 bcast2(float a) {
    u64 r; asm("mov.b64 %0, {%1, %1};" : "=l"(r) : "f"(a)); return r;
}
__device__ __forceinline__ void ffma2(u64& d, u64 a, u64 b) {
    asm("fma.rn.f32x2 %0, %1, %2, %0;" : "+l"(d) : "l"(a), "l"(b));
}
__device__ __forceinline__ float2 unpk(u64 v) {
    float2 f; asm("mov.b64 {%0, %1}, %2;" : "=f"(f.x), "=f"(f.y) : "l"(v)); return f;
}

__device__ __forceinline__ float gelu_exact(float x) {
    return 0.5f * x * (1.0f + erff(x * 0.70710678118654752440f));
}

#define PFMA8(ACC, AP, BA, BB)       \
    ffma2(ACC[0], AP, BA.x);         \
    ffma2(ACC[1], AP, BA.y);         \
    ffma2(ACC[2], AP, BB.x);         \
    ffma2(ACC[3], AP, BB.y);

#define ZERO_ACC2(A)                                  \
    _Pragma("unroll") for (int _r = 0; _r < 4; _r++)  \
    _Pragma("unroll") for (int _j = 0; _j < 4; _j++) A[_r][_j] = 0ULL;

#define UNPACK8(X, ACCR)                       \
    { float2 _p;                               \
      _p = unpk(ACCR[0]); X[0] = _p.x; X[1] = _p.y; \
      _p = unpk(ACCR[1]); X[2] = _p.x; X[3] = _p.y; \
      _p = unpk(ACCR[2]); X[4] = _p.x; X[5] = _p.y; \
      _p = unpk(ACCR[3]); X[6] = _p.x; X[7] = _p.y; }

// ---------------------------------------------------------------------------
// 64x128 GEMM tile (packed f32x2): C[64,128] = A0@W0
// ---------------------------------------------------------------------------
__device__ __forceinline__ void gemm64p(
    const float* __restrict__ A0,
    const float* __restrict__ W0g,
    float* __restrict__ sW,          // smem, >=1024 floats used
    u64 acc[4][4], int tid)
{
    const int ty = tid >> 4, tx = tid & 15;
    const int wr = tid >> 5;
    const int wc = (tid & 31) << 2;

#pragma unroll 1
    for (int kc = 0; kc < 16; kc++) {
        __syncthreads();
        st4(sW + wr * 128 + wc, ld4(W0g + (kc * 8 + wr) * 128 + wc));
        __syncthreads();
#pragma unroll
        for (int k4 = 0; k4 < 8; k4 += 4) {
            float4 a0[4];
#pragma unroll
            for (int r = 0; r < 4; r++)
                a0[r] = ld4(A0 + (ty * 4 + r) * 128 + kc * 8 + k4);
#pragma unroll
            for (int kk = 0; kk < 4; kk++) {
                const int k = k4 + kk;
                ulonglong2 b0a = ld2u64(sW + k * 128 + tx * 4);
                ulonglong2 b0b = ld2u64(sW + k * 128 + 64 + tx * 4);
#pragma unroll
                for (int r = 0; r < 4; r++) {
                    u64 ap = bcast2((&a0[r].x)[kk]);
                    PFMA8(acc[r], ap, b0a, b0b);
                }
            }
        }
    }
}

// Dual-OUTPUT variant: accS = A@W0, accD = A@W1 (shares A loads).
__device__ __forceinline__ void gemm64p_2w(
    const float* __restrict__ A0,
    const float* __restrict__ W0g, const float* __restrict__ W1g,
    float* __restrict__ sW, u64 accS[4][4], u64 accD[4][4], int tid)
{
    const int ty = tid >> 4, tx = tid & 15;
    const int wr = tid >> 5;
    const int wc = (tid & 31) << 2;

#pragma unroll 1
    for (int kc = 0; kc < 16; kc++) {
        __syncthreads();
        st4(sW + wr * 128 + wc, ld4(W0g + (kc * 8 + wr) * 128 + wc));
        st4(sW + 1024 + wr * 128 + wc, ld4(W1g + (kc * 8 + wr) * 128 + wc));
        __syncthreads();
#pragma unroll
        for (int k4 = 0; k4 < 8; k4 += 4) {
            float4 a0[4];
#pragma unroll
            for (int r = 0; r < 4; r++)
                a0[r] = ld4(A0 + (ty * 4 + r) * 128 + kc * 8 + k4);
#pragma unroll
            for (int kk = 0; kk < 4; kk++) {
                const int k = k4 + kk;
                ulonglong2 b0a = ld2u64(sW + k * 128 + tx * 4);
                ulonglong2 b0b = ld2u64(sW + k * 128 + 64 + tx * 4);
                ulonglong2 b1a = ld2u64(sW + 1024 + k * 128 + tx * 4);
                ulonglong2 b1b = ld2u64(sW + 1024 + k * 128 + 64 + tx * 4);
#pragma unroll
                for (int r = 0; r < 4; r++) {
                    u64 ap = bcast2((&a0[r].x)[kk]);
                    PFMA8(accS[r], ap, b0a, b0b);
                    PFMA8(accD[r], ap, b1a, b1b);
                }
            }
        }
    }
}

// ---------------------------------------------------------------------------
__global__ void zero_upd_kernel() {
    int i = blockIdx.x * blockDim.x + threadIdx.x;
    if (i < NN * HH / 4) reinterpret_cast<float4*>(g_upd)[i] = make_float4(0.f, 0.f, 0.f, 0.f);
}

// Composite weights: g_As = Ws@W1a, g_Gs = Ws@Wg1a, g_Ad = Wd@W1b, g_Gd = Wd@Wg1b
__global__ __launch_bounds__(256, 2) void compose_kernel(
    const float* __restrict__ Ws, const float* __restrict__ Wd,
    const float* __restrict__ W1a, const float* __restrict__ Wg1a,
    const float* __restrict__ W1b, const float* __restrict__ Wg1b)
{
    __shared__ float sA[64 * 128];
    __shared__ float sW[1024];
    const int mat = blockIdx.x >> 1, half = blockIdx.x & 1;
    const float* L = (mat < 2) ? Ws : Wd;
    const float* R = (mat == 0) ? W1a : (mat == 1) ? Wg1a : (mat == 2) ? W1b : Wg1b;
    float* O = (mat == 0) ? g_As : (mat == 1) ? g_Gs : (mat == 2) ? g_Ad : g_Gd;

    const int tid = threadIdx.x, warp = tid >> 5, lane = tid & 31;
    const int ty = tid >> 4, tx = tid & 15;
#pragma unroll
    for (int i = 0; i < 8; i++) {
        int r = warp + i * 8;
        st4(sA + r * 128 + lane * 4, ld4(L + (half * 64 + r) * 128 + lane * 4));
    }
    u64 acc[4][4];
    ZERO_ACC2(acc);
    gemm64p(sA, R, sW, acc, tid);
#pragma unroll
    for (int r = 0; r < 4; r++) {
        int row = half * 64 + ty * 4 + r;
        float x[8]; UNPACK8(x, acc[r]);
        st4(O + row * 128 + tx * 4,      make_float4(x[0], x[1], x[2], x[3]));
        st4(O + row * 128 + 64 + tx * 4, make_float4(x[4], x[5], x[6], x[7]));
    }
}

// folded biases: g_fb[0]=b_src@W1a, [1]=b_src@Wg1a, [2]=b_dst@W1b, [3]=b_dst@Wg1b
__global__ void bias_kernel(
    const float* __restrict__ bsrc, const float* __restrict__ bdst,
    const float* __restrict__ W1a, const float* __restrict__ Wg1a,
    const float* __restrict__ W1b, const float* __restrict__ Wg1b)
{
    const int mat = blockIdx.x, n = threadIdx.x;
    const float* bv = (mat < 2) ? bsrc : bdst;
    const float* R = (mat == 0) ? W1a : (mat == 1) ? Wg1a : (mat == 2) ? W1b : Wg1b;
    float s = 0.f;
    for (int j = 0; j < 128; j++) s = fmaf(bv[j], R[j * 128 + n], s);
    g_fb[mat][n] = s;
}

// Node tables: g_Us[n] = [feat@As + fb0 | feat@Gs + fb1]; g_Ud similarly.
// grid = 2*1563: blocks >= 1563 compute the dst table.
__global__ __launch_bounds__(256, 2) void node_kernel(const float* __restrict__ feat)
{
    __shared__ float sF[64 * 128];
    __shared__ float sW[2 * 1024];
    const int tid = threadIdx.x, warp = tid >> 5, lane = tid & 31;
    const int ty = tid >> 4, tx = tid & 15;
    const int which = (blockIdx.x >= 1563) ? 1 : 0;
    const size_t row0 = (size_t)(blockIdx.x - which * 1563) * 64;

    const float* WA = which ? g_Ad : g_As;
    const float* WG = which ? g_Gd : g_Gs;
    const float* f1 = which ? g_fb[2] : g_fb[0];
    const float* fg = which ? g_fb[3] : g_fb[1];
    float* table = which ? g_Ud : g_Us;

#pragma unroll
    for (int i = 0; i < 8; i++) {
        int r = warp + i * 8;
        size_t gr = row0 + r;
        float4 v = make_float4(0.f, 0.f, 0.f, 0.f);
        if (gr < NN) v = ld4(feat + gr * 128 + lane * 4);
        st4(sF + r * 128 + lane * 4, v);
    }
    u64 accU[4][4], accG[4][4];
    ZERO_ACC2(accU); ZERO_ACC2(accG);
    gemm64p_2w(sF, WA, WG, sW, accU, accG, tid);

    float4 b10 = ld4(f1 + tx * 4), b11 = ld4(f1 + 64 + tx * 4);
    float4 bg0 = ld4(fg + tx * 4), bg1v = ld4(fg + 64 + tx * 4);
#pragma unroll
    for (int r = 0; r < 4; r++) {
        size_t gr = row0 + ty * 4 + r;
        if (gr < NN) {
            float xu[8], xg[8];
            UNPACK8(xu, accU[r]); UNPACK8(xg, accG[r]);
            st4(table + gr * 256 + tx * 4,
                make_float4(xu[0] + b10.x, xu[1] + b10.y, xu[2] + b10.z, xu[3] + b10.w));
            st4(table + gr * 256 + 64 + tx * 4,
                make_float4(xu[4] + b11.x, xu[5] + b11.y, xu[6] + b11.z, xu[7] + b11.w));
            st4(table + gr * 256 + 128 + tx * 4,
                make_float4(xg[0] + bg0.x, xg[1] + bg0.y, xg[2] + bg0.z, xg[3] + bg0.w));
            st4(table + gr * 256 + 192 + tx * 4,
                make_float4(xg[4] + bg1v.x, xg[5] + bg1v.y, xg[6] + bg1v.z, xg[7] + bg1v.w));
        }
    }
}

// Fused edge pipeline: gather precomputed linear parts, 2 GEMMs, LN, gated scatter.
__global__ __launch_bounds__(256, 3) void edge_kernel(
    const int* __restrict__ esrc, const int* __restrict__ edst,
    const float* __restrict__ b1,
    const float* __restrict__ W2,  const float* __restrict__ b2,
    const float* __restrict__ W3,  const float* __restrict__ b3,
    const float* __restrict__ lng, const float* __restrict__ lnb,
    const float* __restrict__ bg1, const float* __restrict__ Wg2,
    const float* __restrict__ bg2)
{
    __shared__ float sH[64 * 128];
    __shared__ float sW[1024];
    __shared__ float sGate[64];
    __shared__ int   sDst[64];

    const int tid = threadIdx.x, warp = tid >> 5, lane = tid & 31;
    const int ty = tid >> 4, tx = tid & 15;
    const int e0 = blockIdx.x * 64;

    // ---- gather + h1 + gate pre-reduction ----
    {
        float4 b1v = ld4(b1 + lane * 4);
        float4 bgv = ld4(bg1 + lane * 4);
        float4 wgv = ld4(Wg2 + lane * 4);
#pragma unroll
        for (int i = 0; i < 8; i++) {
            int r = warp + i * 8;
            int s = esrc[e0 + r];
            int d = edst[e0 + r];
            const float* us = g_Us + (size_t)s * 256;
            const float* ud = g_Ud + (size_t)d * 256;
            float4 a = ld4(us + lane * 4);
            float4 bq = ld4(ud + lane * 4);
            float4 a2 = ld4(us + 128 + lane * 4);
            float4 b2q = ld4(ud + 128 + lane * 4);
            float4 h;
            h.x = gelu_exact(a.x + bq.x + b1v.x);
            h.y = gelu_exact(a.y + bq.y + b1v.y);
            h.z = gelu_exact(a.z + bq.z + b1v.z);
            h.w = gelu_exact(a.w + bq.w + b1v.w);
            st4(sH + r * 128 + lane * 4, h);
            float sg = gelu_exact(a2.x + b2q.x + bgv.x) * wgv.x
                     + gelu_exact(a2.y + b2q.y + bgv.y) * wgv.y
                     + gelu_exact(a2.z + b2q.z + bgv.z) * wgv.z
                     + gelu_exact(a2.w + b2q.w + bgv.w) * wgv.w;
#pragma unroll
            for (int off = 1; off < 32; off <<= 1)
                sg += __shfl_xor_sync(0xffffffffu, sg, off);
            if (lane == 0) { sGate[r] = sg; sDst[r] = d; }
        }
    }
    // (gemm64p's leading __syncthreads orders gather writes before reads)

    u64 acc[4][4];

    // ---- h2 = gelu(h1@W2 + b2) -> sH (overwrite after barrier) ----
    ZERO_ACC2(acc);
    gemm64p(sH, W2, sW, acc, tid);
    __syncthreads();   // all reads of h1 done before overwrite
    {
        float4 bb0 = ld4(b2 + tx * 4), bb1 = ld4(b2 + 64 + tx * 4);
#pragma unroll
        for (int r = 0; r < 4; r++) {
            int row = ty * 4 + r;
            float x[8]; UNPACK8(x, acc[r]);
            float4 h;
            h.x = gelu_exact(x[0] + bb0.x); h.y = gelu_exact(x[1] + bb0.y);
            h.z = gelu_exact(x[2] + bb0.z); h.w = gelu_exact(x[3] + bb0.w);
            st4(sH + row * 128 + tx * 4, h);
            h.x = gelu_exact(x[4] + bb1.x); h.y = gelu_exact(x[5] + bb1.y);
            h.z = gelu_exact(x[6] + bb1.z); h.w = gelu_exact(x[7] + bb1.w);
            st4(sH + row * 128 + 64 + tx * 4, h);
        }
    }

    // ---- m = layernorm(h2@W3 + b3); msg = gate*m; scatter-add ----
    ZERO_ACC2(acc);
    gemm64p(sH, W3, sW, acc, tid);
    {
        float bg2v = bg2[0];
        float4 b30 = ld4(b3 + tx * 4),  b31 = ld4(b3 + 64 + tx * 4);
        float4 g0  = ld4(lng + tx * 4), g1  = ld4(lng + 64 + tx * 4);
        float4 e0v = ld4(lnb + tx * 4), e1v = ld4(lnb + 64 + tx * 4);
#pragma unroll
        for (int r = 0; r < 4; r++) {
            int row = ty * 4 + r;
            float x[8]; UNPACK8(x, acc[r]);
            x[0] += b30.x; x[1] += b30.y; x[2] += b30.z; x[3] += b30.w;
            x[4] += b31.x; x[5] += b31.y; x[6] += b31.z; x[7] += b31.w;
            float s = 0.f, ss = 0.f;
#pragma unroll
            for (int j = 0; j < 8; j++) { s += x[j]; ss += x[j] * x[j]; }
#pragma unroll
            for (int off = 1; off < 16; off <<= 1) {
                s  += __shfl_xor_sync(0xffffffffu, s, off);
                ss += __shfl_xor_sync(0xffffffffu, ss, off);
            }
            float m = s * 0.0078125f;
            float var = ss * 0.0078125f - m * m;
            float rstd = rsqrtf(var + 1e-5f);
            float gv = 1.0f / (1.0f + expf(-(sGate[row] + bg2v)));
            float* up = g_upd + (size_t)sDst[row] * 128;
            atomicAdd(up + tx * 4 + 0,      ((x[0] - m) * rstd * g0.x + e0v.x) * gv);
            atomicAdd(up + tx * 4 + 1,      ((x[1] - m) * rstd * g0.y + e0v.y) * gv);
            atomicAdd(up + tx * 4 + 2,      ((x[2] - m) * rstd * g0.z + e0v.z) * gv);
            atomicAdd(up + tx * 4 + 3,      ((x[3] - m) * rstd * g0.w + e0v.w) * gv);
            atomicAdd(up + 64 + tx * 4 + 0, ((x[4] - m) * rstd * g1.x + e1v.x) * gv);
            atomicAdd(up + 64 + tx * 4 + 1, ((x[5] - m) * rstd * g1.y + e1v.y) * gv);
            atomicAdd(up + 64 + tx * 4 + 2, ((x[6] - m) * rstd * g1.z + e1v.z) * gv);
            atomicAdd(up + 64 + tx * 4 + 3, ((x[7] - m) * rstd * g1.w + e1v.w) * gv);
        }
    }
}

// out = upd@W_out + b_out
__global__ __launch_bounds__(256, 2) void out_kernel(
    const float* __restrict__ Wout, const float* __restrict__ bout,
    float* __restrict__ out)
{
    __shared__ float sU[64 * 128];
    __shared__ float sW[1024];
    const int tid = threadIdx.x, warp = tid >> 5, lane = tid & 31;
    const int ty = tid >> 4, tx = tid & 15;
    const size_t row0 = (size_t)blockIdx.x * 64;

#pragma unroll
    for (int i = 0; i < 8; i++) {
        int r = warp + i * 8;
        size_t gr = row0 + r;
        float4 v = make_float4(0.f, 0.f, 0.f, 0.f);
        if (gr < NN) v = ld4(g_upd + gr * 128 + lane * 4);
        st4(sU + r * 128 + lane * 4, v);
    }
    u64 acc[4][4];
    ZERO_ACC2(acc);
    gemm64p(sU, Wout, sW, acc, tid);

    float4 b0 = ld4(bout + tx * 4), b1v = ld4(bout + 64 + tx * 4);
#pragma unroll
    for (int r = 0; r < 4; r++) {
        size_t gr = row0 + ty * 4 + r;
        if (gr < NN) {
            float x[8]; UNPACK8(x, acc[r]);
            st4(out + gr * 128 + tx * 4,
                make_float4(x[0] + b0.x, x[1] + b0.y, x[2] + b0.z, x[3] + b0.w));
            st4(out + gr * 128 + 64 + tx * 4,
                make_float4(x[4] + b1v.x, x[5] + b1v.y, x[6] + b1v.z, x[7] + b1v.w));
        }
    }
}

extern "C" void kernel_launch(void* const* d_in, const int* in_sizes, int n_in,
                              void* d_out, int out_size)
{
    const float* feat  = (const float*)d_in[0];
    const int*   esrc  = (const int*)d_in[1];
    const int*   edst  = (const int*)d_in[2];
    const float* W_src = (const float*)d_in[3];
    const float* b_src = (const float*)d_in[4];
    const float* W_dst = (const float*)d_in[5];
    const float* b_dst = (const float*)d_in[6];
    const float* W1a   = (const float*)d_in[7];
    const float* W1b   = (const float*)d_in[8];
    const float* b1    = (const float*)d_in[9];
    const float* W2    = (const float*)d_in[10];
    const float* b2    = (const float*)d_in[11];
    const float* W3    = (const float*)d_in[12];
    const float* b3    = (const float*)d_in[13];
    const float* ln_g  = (const float*)d_in[14];
    const float* ln_b  = (const float*)d_in[15];
    const float* Wg1a  = (const float*)d_in[16];
    const float* Wg1b  = (const float*)d_in[17];
    const float* bg1   = (const float*)d_in[18];
    const float* Wg2   = (const float*)d_in[19];
    const float* bg2   = (const float*)d_in[20];
    const float* W_out = (const float*)d_in[21];
    const float* b_out = (const float*)d_in[22];
    float* out = (float*)d_out;

    compose_kernel<<<8, 256>>>(W_src, W_dst, W1a, Wg1a, W1b, Wg1b);
    bias_kernel<<<4, 128>>>(b_src, b_dst, W1a, Wg1a, W1b, Wg1b);
    zero_upd_kernel<<<(NN * HH / 4 + 255) / 256, 256>>>();
    node_kernel<<<2 * 1563, 256>>>(feat);
    edge_kernel<<<EE / 64, 256>>>(esrc, edst, b1, W2, b2, W3, b3,
                                  ln_g, ln_b, bg1, Wg2, bg2);
    out_kernel<<<(NN + 63) / 64, 256>>>(W_out, b_out, out);
}